// round 1
// baseline (speedup 1.0000x reference)
#include <cuda_runtime.h>
#include <math.h>

// Problem constants (fixed shapes from setup_inputs)
#define DIN   768
#define DOUT  3072
#define MTOT  12608   // 64 * 197

// Masked-weight scratch (allocation-free rule: __device__ global)
__device__ float g_wmask[DOUT * DIN];

// ---------------------------------------------------------------------------
// Kernel 1: 2:4 mask. One thread per group of 4 weights. Zero the two
// smallest |w| in each group; strict '<' argmin matches jax.lax.top_k's
// stable lowest-index tie-breaking.
// ---------------------------------------------------------------------------
__global__ void mask24_kernel(const float* __restrict__ w) {
    int g = blockIdx.x * blockDim.x + threadIdx.x;
    const int n_groups = DOUT * DIN / 4;
    if (g >= n_groups) return;

    float4 wv = reinterpret_cast<const float4*>(w)[g];
    float v[4] = {wv.x, wv.y, wv.z, wv.w};
    float a[4] = {fabsf(wv.x), fabsf(wv.y), fabsf(wv.z), fabsf(wv.w)};

    // smallest (lowest index on ties)
    int i0 = 0;
#pragma unroll
    for (int i = 1; i < 4; i++) if (a[i] < a[i0]) i0 = i;
    // second smallest among remaining (lowest index on ties)
    int i1 = (i0 == 0) ? 1 : 0;
#pragma unroll
    for (int i = 0; i < 4; i++) if (i != i0 && a[i] < a[i1]) i1 = i;

    v[i0] = 0.0f;
    v[i1] = 0.0f;
    reinterpret_cast<float4*>(g_wmask)[g] = make_float4(v[0], v[1], v[2], v[3]);
}

// ---------------------------------------------------------------------------
// Kernel 2: SGEMM  C[m,n] = sum_k A[m,k] * W[n,k] + bias[n]
// Tiles: BM=128, BN=128, BK=16. 256 threads, each computes an 8x8 micro-tile.
// Both operands are K-contiguous, so tiles are loaded K-major and stored
// transposed into smem (stride 132 to break the 4-way store conflict).
// ---------------------------------------------------------------------------
#define BM 128
#define BN 128
#define BK 16
#define SSTR 132   // smem row stride in floats (padded)

__global__ __launch_bounds__(256, 2)
void sgemm24_kernel(const float* __restrict__ A,
                    const float* __restrict__ bias,
                    float* __restrict__ C) {
    __shared__ float As[BK][SSTR];
    __shared__ float Bs[BK][SSTR];

    const int tid = threadIdx.x;
    const int tx  = tid & 15;   // 0..15 -> N direction
    const int ty  = tid >> 4;   // 0..15 -> M direction
    const int m0  = blockIdx.y * BM;
    const int n0  = blockIdx.x * BN;

    const float* __restrict__ B = g_wmask;

    float acc[8][8];
#pragma unroll
    for (int i = 0; i < 8; i++)
#pragma unroll
        for (int j = 0; j < 8; j++) acc[i][j] = 0.0f;

    for (int k0 = 0; k0 < DIN; k0 += BK) {
        // --- load A tile: 128 rows x 16 cols = 512 float4 slots ---
#pragma unroll
        for (int s = 0; s < 2; s++) {
            int slot = s * 256 + tid;
            int row  = slot >> 2;
            int c4   = (slot & 3) << 2;
            int m    = m0 + row;
            float4 v = make_float4(0.f, 0.f, 0.f, 0.f);
            if (m < MTOT)
                v = reinterpret_cast<const float4*>(A + (size_t)m * DIN + k0 + c4)[0];
            As[c4 + 0][row] = v.x;
            As[c4 + 1][row] = v.y;
            As[c4 + 2][row] = v.z;
            As[c4 + 3][row] = v.w;
        }
        // --- load B tile (masked weight): no bounds needed, 3072 % 128 == 0 ---
#pragma unroll
        for (int s = 0; s < 2; s++) {
            int slot = s * 256 + tid;
            int row  = slot >> 2;
            int c4   = (slot & 3) << 2;
            int n    = n0 + row;
            float4 v = reinterpret_cast<const float4*>(B + (size_t)n * DIN + k0 + c4)[0];
            Bs[c4 + 0][row] = v.x;
            Bs[c4 + 1][row] = v.y;
            Bs[c4 + 2][row] = v.z;
            Bs[c4 + 3][row] = v.w;
        }
        __syncthreads();

        // --- compute ---
#pragma unroll
        for (int kk = 0; kk < BK; kk++) {
            float ra[8], rb[8];
#pragma unroll
            for (int i = 0; i < 8; i++) ra[i] = As[kk][ty * 8 + i];
#pragma unroll
            for (int j = 0; j < 8; j++) rb[j] = Bs[kk][tx * 8 + j];
#pragma unroll
            for (int i = 0; i < 8; i++)
#pragma unroll
                for (int j = 0; j < 8; j++)
                    acc[i][j] += ra[i] * rb[j];
        }
        __syncthreads();
    }

    // --- epilogue: add bias, vectorized stores ---
    float bv[8];
#pragma unroll
    for (int j = 0; j < 8; j++) bv[j] = bias[n0 + tx * 8 + j];

#pragma unroll
    for (int i = 0; i < 8; i++) {
        int m = m0 + ty * 8 + i;
        if (m < MTOT) {
            float* cp = C + (size_t)m * DOUT + n0 + tx * 8;
            float4 o0, o1;
            o0.x = acc[i][0] + bv[0];
            o0.y = acc[i][1] + bv[1];
            o0.z = acc[i][2] + bv[2];
            o0.w = acc[i][3] + bv[3];
            o1.x = acc[i][4] + bv[4];
            o1.y = acc[i][5] + bv[5];
            o1.z = acc[i][6] + bv[6];
            o1.w = acc[i][7] + bv[7];
            reinterpret_cast<float4*>(cp)[0] = o0;
            reinterpret_cast<float4*>(cp)[1] = o1;
        }
    }
}

// ---------------------------------------------------------------------------
extern "C" void kernel_launch(void* const* d_in, const int* in_sizes, int n_in,
                              void* d_out, int out_size) {
    // Identify inputs robustly by element count.
    const float* x = nullptr;
    const float* w = nullptr;
    const float* b = nullptr;
    for (int i = 0; i < n_in; i++) {
        if (in_sizes[i] == DOUT * DIN)      w = (const float*)d_in[i];
        else if (in_sizes[i] == DOUT)       b = (const float*)d_in[i];
        else                                x = (const float*)d_in[i];
    }
    float* out = (float*)d_out;

    // 1) compute masked weight
    const int n_groups = DOUT * DIN / 4;
    mask24_kernel<<<(n_groups + 255) / 256, 256>>>(w);

    // 2) GEMM + bias
    dim3 grid(DOUT / BN, (MTOT + BM - 1) / BM);
    sgemm24_kernel<<<grid, 256>>>(x, b, out);
}

// round 6
// speedup vs baseline: 2.9396x; 2.9396x over previous
#include <cuda_runtime.h>
#include <cuda_bf16.h>
#include <cstdint>
#include <math.h>

// ---------------------------------------------------------------------------
// Problem constants
// ---------------------------------------------------------------------------
#define DIN   768
#define DOUT  3072
#define MTOT  12608          // 64 * 197
#define MPAD  12672          // 99 * 128
#define BM    128
#define BN    128
#define BK    64
#define NCHUNK (DIN / BK)    // 12
#define ROWU4 (DIN / 8)      // 96 uint4 per bf16 row
#define TILE_B  16384        // 128 rows * 128 B
#define STAGE_B (4 * TILE_B) // xhi, xlo, whi, wlo tiles
#define NSTAGE  2
#define SMEM_TOTAL (NSTAGE * STAGE_B)   // 131072 B

// ---------------------------------------------------------------------------
// Split operand scratch (allocation-free rule: __device__ globals)
// ---------------------------------------------------------------------------
__device__ __align__(16) __nv_bfloat16 g_xhi[(size_t)MPAD * DIN];
__device__ __align__(16) __nv_bfloat16 g_xlo[(size_t)MPAD * DIN];
__device__ __align__(16) __nv_bfloat16 g_whi[(size_t)DOUT * DIN];
__device__ __align__(16) __nv_bfloat16 g_wlo[(size_t)DOUT * DIN];

// ---------------------------------------------------------------------------
// PTX helpers (all valid on baseline compute_103 — no arch-specific features)
// ---------------------------------------------------------------------------
__device__ __forceinline__ uint32_t smem_u32(const void* p) {
    uint32_t a;
    asm("{ .reg .u64 t; cvta.to.shared.u64 t, %1; cvt.u32.u64 %0, t; }"
        : "=r"(a) : "l"(p));
    return a;
}

__device__ __forceinline__ void cp16(uint32_t sa, const void* ga) {
    asm volatile("cp.async.cg.shared.global [%0], [%1], 16;"
                 :: "r"(sa), "l"(ga) : "memory");
}
__device__ __forceinline__ void cp_commit() {
    asm volatile("cp.async.commit_group;" ::: "memory");
}

__device__ __forceinline__ void ldmx4(uint32_t* r, uint32_t addr) {
    asm volatile("ldmatrix.sync.aligned.m8n8.x4.shared.b16 {%0,%1,%2,%3}, [%4];"
                 : "=r"(r[0]), "=r"(r[1]), "=r"(r[2]), "=r"(r[3]) : "r"(addr));
}

__device__ __forceinline__ void mma_bf16(float* c, const uint32_t* a, const uint32_t* b) {
    asm volatile("mma.sync.aligned.m16n8k16.row.col.f32.bf16.bf16.f32 "
                 "{%0,%1,%2,%3}, {%4,%5,%6,%7}, {%8,%9}, {%0,%1,%2,%3};"
                 : "+f"(c[0]), "+f"(c[1]), "+f"(c[2]), "+f"(c[3])
                 : "r"(a[0]), "r"(a[1]), "r"(a[2]), "r"(a[3]),
                   "r"(b[0]), "r"(b[1]));
}

// ---------------------------------------------------------------------------
// bf16 split helpers
// ---------------------------------------------------------------------------
__device__ __forceinline__ void split2(float v, __nv_bfloat16& hi, __nv_bfloat16& lo) {
    hi = __float2bfloat16_rn(v);
    lo = __float2bfloat16_rn(v - __bfloat162float(hi));
}
__device__ __forceinline__ uint32_t pack2(__nv_bfloat16 a, __nv_bfloat16 b) {
    return (uint32_t)__bfloat16_as_ushort(a) | ((uint32_t)__bfloat16_as_ushort(b) << 16);
}

// ---------------------------------------------------------------------------
// Kernel 1: split x into hi/lo bf16, zero-pad rows [MTOT, MPAD)
// ---------------------------------------------------------------------------
__global__ void splitx_kernel(const float* __restrict__ x) {
    int g = blockIdx.x * blockDim.x + threadIdx.x;
    const int NG = MPAD * (DIN / 4);
    if (g >= NG) return;
    int row = g / (DIN / 4);
    float4 v = make_float4(0.f, 0.f, 0.f, 0.f);
    if (row < MTOT) v = reinterpret_cast<const float4*>(x)[g];
    __nv_bfloat16 h0, h1, h2, h3, l0, l1, l2, l3;
    split2(v.x, h0, l0); split2(v.y, h1, l1);
    split2(v.z, h2, l2); split2(v.w, h3, l3);
    reinterpret_cast<uint2*>(g_xhi)[g] = make_uint2(pack2(h0, h1), pack2(h2, h3));
    reinterpret_cast<uint2*>(g_xlo)[g] = make_uint2(pack2(l0, l1), pack2(l2, l3));
}

// ---------------------------------------------------------------------------
// Kernel 2: 2:4 mask (strict-< argmin matches top_k tie-break) + split
// ---------------------------------------------------------------------------
__global__ void maskw_kernel(const float* __restrict__ w) {
    int g = blockIdx.x * blockDim.x + threadIdx.x;
    const int NG = DOUT * DIN / 4;
    if (g >= NG) return;
    float4 wv = reinterpret_cast<const float4*>(w)[g];
    float v[4] = {wv.x, wv.y, wv.z, wv.w};
    float a[4] = {fabsf(wv.x), fabsf(wv.y), fabsf(wv.z), fabsf(wv.w)};
    int i0 = 0;
#pragma unroll
    for (int i = 1; i < 4; i++) if (a[i] < a[i0]) i0 = i;
    int i1 = (i0 == 0) ? 1 : 0;
#pragma unroll
    for (int i = 0; i < 4; i++) if (i != i0 && a[i] < a[i1]) i1 = i;
    v[i0] = 0.0f; v[i1] = 0.0f;
    __nv_bfloat16 h[4], l[4];
#pragma unroll
    for (int i = 0; i < 4; i++) split2(v[i], h[i], l[i]);
    reinterpret_cast<uint2*>(g_whi)[g] = make_uint2(pack2(h[0], h[1]), pack2(h[2], h[3]));
    reinterpret_cast<uint2*>(g_wlo)[g] = make_uint2(pack2(l[0], l[1]), pack2(l[2], l[3]));
}

// ---------------------------------------------------------------------------
// Chunk loader: 4 tiles (xhi/xlo/whi/wlo), each 128 rows x 128 B, SW128
// swizzled, via cp.async. 16 x 16B per thread.
// ---------------------------------------------------------------------------
__device__ __forceinline__ void load_chunk(int c, int s, uint32_t sb,
                                           int m0, int n0, int tid) {
    const uint4* srcs[4] = {
        reinterpret_cast<const uint4*>(g_xhi) + (size_t)m0 * ROWU4,
        reinterpret_cast<const uint4*>(g_xlo) + (size_t)m0 * ROWU4,
        reinterpret_cast<const uint4*>(g_whi) + (size_t)n0 * ROWU4,
        reinterpret_cast<const uint4*>(g_wlo) + (size_t)n0 * ROWU4};
#pragma unroll
    for (int tile = 0; tile < 4; tile++) {
        const uint4* src = srcs[tile] + c * 8;
        uint32_t tb = sb + s * STAGE_B + tile * TILE_B;
#pragma unroll
        for (int i = 0; i < 4; i++) {
            int idx = i * 256 + tid;
            int row = idx >> 3;
            int c16 = idx & 7;
            uint32_t off = (uint32_t)(row * 128 + c16 * 16);
            off ^= (off >> 3) & 0x70;
            cp16(tb + off, src + (size_t)row * ROWU4 + c16);
        }
    }
}

// ---------------------------------------------------------------------------
// Kernel 3: HMMA bf16 GEMM with 3-pass split accumulation.
// 8 warps, warp grid 2(M) x 4(N), warp tile 64x32.
// ---------------------------------------------------------------------------
__global__ __launch_bounds__(256, 1)
void gemm_hmma_kernel(const float* __restrict__ bias, float* __restrict__ C) {
    extern __shared__ __align__(1024) char smem[];
    const uint32_t sb = smem_u32(smem);
    const int tid = threadIdx.x;
    const int lane = tid & 31;
    const int wid = tid >> 5;
    const int wm = wid & 1;        // 0..1  (M)
    const int wn = wid >> 1;       // 0..3  (N)
    const int m0 = blockIdx.y * BM;
    const int n0 = blockIdx.x * BN;

    float acc[4][4][4];
#pragma unroll
    for (int t = 0; t < 4; t++)
#pragma unroll
        for (int j = 0; j < 4; j++)
#pragma unroll
            for (int k = 0; k < 4; k++) acc[t][j][k] = 0.0f;

    // prologue: 2 chunks in flight
    load_chunk(0, 0, sb, m0, n0, tid); cp_commit();
    load_chunk(1, 1, sb, m0, n0, tid); cp_commit();

    for (int c = 0; c < NCHUNK; c++) {
        if (c == NCHUNK - 1) asm volatile("cp.async.wait_group 0;" ::: "memory");
        else                 asm volatile("cp.async.wait_group 1;" ::: "memory");
        __syncthreads();

        const int s = c & 1;
        const uint32_t aH = sb + s * STAGE_B;
        const uint32_t aL = aH + TILE_B;
        const uint32_t bH = aH + 2 * TILE_B;
        const uint32_t bL = aH + 3 * TILE_B;

#pragma unroll
        for (int ks = 0; ks < 4; ks++) {
            uint32_t ah[4][4], al[4][4];
#pragma unroll
            for (int t = 0; t < 4; t++) {
                uint32_t off = (uint32_t)((wm * 64 + t * 16 + (lane & 15)) * 128
                                          + ks * 32 + (lane >> 4) * 16);
                off ^= (off >> 3) & 0x70;
                ldmx4(ah[t], aH + off);
                ldmx4(al[t], aL + off);
            }
            uint32_t bh[4][2], bl[4][2];
#pragma unroll
            for (int jj = 0; jj < 2; jj++) {
                uint32_t row = (uint32_t)(wn * 32 + jj * 16
                                          + ((lane >> 4) & 1) * 8 + (lane & 7));
                uint32_t off = row * 128 + ks * 32 + ((lane >> 3) & 1) * 16;
                off ^= (off >> 3) & 0x70;
                uint32_t r[4];
                ldmx4(r, bH + off);
                bh[2 * jj][0] = r[0]; bh[2 * jj][1] = r[1];
                bh[2 * jj + 1][0] = r[2]; bh[2 * jj + 1][1] = r[3];
                ldmx4(r, bL + off);
                bl[2 * jj][0] = r[0]; bl[2 * jj][1] = r[1];
                bl[2 * jj + 1][0] = r[2]; bl[2 * jj + 1][1] = r[3];
            }
            // 3 accumulation passes: hi*hi, hi*lo, lo*hi
#pragma unroll
            for (int t = 0; t < 4; t++)
#pragma unroll
                for (int j = 0; j < 4; j++) mma_bf16(acc[t][j], ah[t], bh[j]);
#pragma unroll
            for (int t = 0; t < 4; t++)
#pragma unroll
                for (int j = 0; j < 4; j++) mma_bf16(acc[t][j], ah[t], bl[j]);
#pragma unroll
            for (int t = 0; t < 4; t++)
#pragma unroll
                for (int j = 0; j < 4; j++) mma_bf16(acc[t][j], al[t], bh[j]);
        }

        if (c + 2 < NCHUNK) {
            __syncthreads();
            load_chunk(c + 2, s, sb, m0, n0, tid);
            cp_commit();
        }
    }

    // epilogue: bias add + float2 stores
    const int mrow = lane >> 2;          // 0..7
    const int ncol = (lane & 3) * 2;
#pragma unroll
    for (int t = 0; t < 4; t++) {
        const int mbase = m0 + wm * 64 + t * 16;
#pragma unroll
        for (int j = 0; j < 4; j++) {
            const int n = n0 + wn * 32 + j * 8 + ncol;
            const float2 bv = *reinterpret_cast<const float2*>(bias + n);
            const int m1 = mbase + mrow;
            if (m1 < MTOT) {
                float2 o = make_float2(acc[t][j][0] + bv.x, acc[t][j][1] + bv.y);
                *reinterpret_cast<float2*>(C + (size_t)m1 * DOUT + n) = o;
            }
            const int m2 = m1 + 8;
            if (m2 < MTOT) {
                float2 o = make_float2(acc[t][j][2] + bv.x, acc[t][j][3] + bv.y);
                *reinterpret_cast<float2*>(C + (size_t)m2 * DOUT + n) = o;
            }
        }
    }
}

// ---------------------------------------------------------------------------
extern "C" void kernel_launch(void* const* d_in, const int* in_sizes, int n_in,
                              void* d_out, int out_size) {
    const float* x = nullptr;
    const float* w = nullptr;
    const float* b = nullptr;
    for (int i = 0; i < n_in; i++) {
        if (in_sizes[i] == DOUT * DIN)  w = (const float*)d_in[i];
        else if (in_sizes[i] == DOUT)   b = (const float*)d_in[i];
        else                            x = (const float*)d_in[i];
    }
    float* out = (float*)d_out;

    cudaFuncSetAttribute(gemm_hmma_kernel,
                         cudaFuncAttributeMaxDynamicSharedMemorySize,
                         SMEM_TOTAL);

    const int ngx = MPAD * (DIN / 4);
    splitx_kernel<<<(ngx + 255) / 256, 256>>>(x);
    const int ngw = DOUT * DIN / 4;
    maskw_kernel<<<(ngw + 255) / 256, 256>>>(w);

    dim3 grid(DOUT / BN, MPAD / BM);
    gemm_hmma_kernel<<<grid, 256, SMEM_TOTAL>>>(b, out);
}

// round 10
// speedup vs baseline: 7.5032x; 2.5524x over previous
#include <cuda_runtime.h>
#include <cuda_fp16.h>
#include <cstdint>
#include <math.h>

// ---------------------------------------------------------------------------
// Problem constants
// ---------------------------------------------------------------------------
#define DIN   768
#define DOUT  3072
#define MTOT  12608          // 64 * 197
#define MPAD  12672          // 99 * 128
#define BM    128
#define BN    128
#define BK    64
#define NCHUNK (DIN / BK)    // 12
#define ROWU4 (DIN / 8)      // 96 uint4 per fp16 row
#define TILE_B  16384        // 128 rows * 128 B
#define STAGE_B (2 * TILE_B) // x tile + w tile
#define NSTAGE  2
#define SMEM_TOTAL (NSTAGE * STAGE_B)   // 65536 B -> 2 CTAs/SM

// ---------------------------------------------------------------------------
// fp16 operand scratch (allocation-free rule: __device__ globals)
// ---------------------------------------------------------------------------
__device__ __align__(16) __half g_xh[(size_t)MPAD * DIN];
__device__ __align__(16) __half g_wh[(size_t)DOUT * DIN];

// ---------------------------------------------------------------------------
// PTX helpers (valid on baseline compute_103)
// ---------------------------------------------------------------------------
__device__ __forceinline__ uint32_t smem_u32(const void* p) {
    uint32_t a;
    asm("{ .reg .u64 t; cvta.to.shared.u64 t, %1; cvt.u32.u64 %0, t; }"
        : "=r"(a) : "l"(p));
    return a;
}

__device__ __forceinline__ void cp16(uint32_t sa, const void* ga) {
    asm volatile("cp.async.cg.shared.global [%0], [%1], 16;"
                 :: "r"(sa), "l"(ga) : "memory");
}
__device__ __forceinline__ void cp_commit() {
    asm volatile("cp.async.commit_group;" ::: "memory");
}

__device__ __forceinline__ void ldmx4(uint32_t* r, uint32_t addr) {
    asm volatile("ldmatrix.sync.aligned.m8n8.x4.shared.b16 {%0,%1,%2,%3}, [%4];"
                 : "=r"(r[0]), "=r"(r[1]), "=r"(r[2]), "=r"(r[3]) : "r"(addr));
}

__device__ __forceinline__ void mma_f16(float* c, const uint32_t* a, const uint32_t* b) {
    asm volatile("mma.sync.aligned.m16n8k16.row.col.f32.f16.f16.f32 "
                 "{%0,%1,%2,%3}, {%4,%5,%6,%7}, {%8,%9}, {%0,%1,%2,%3};"
                 : "+f"(c[0]), "+f"(c[1]), "+f"(c[2]), "+f"(c[3])
                 : "r"(a[0]), "r"(a[1]), "r"(a[2]), "r"(a[3]),
                   "r"(b[0]), "r"(b[1]));
}

__device__ __forceinline__ uint32_t packh2(__half a, __half b) {
    return (uint32_t)__half_as_ushort(a) | ((uint32_t)__half_as_ushort(b) << 16);
}

// ---------------------------------------------------------------------------
// Kernel 1: convert x to fp16, zero-pad rows [MTOT, MPAD)
// ---------------------------------------------------------------------------
__global__ void convx_kernel(const float* __restrict__ x) {
    int g = blockIdx.x * blockDim.x + threadIdx.x;
    const int NG = MPAD * (DIN / 4);
    if (g >= NG) return;
    int row = g / (DIN / 4);
    float4 v = make_float4(0.f, 0.f, 0.f, 0.f);
    if (row < MTOT) v = reinterpret_cast<const float4*>(x)[g];
    reinterpret_cast<uint2*>(g_xh)[g] =
        make_uint2(packh2(__float2half_rn(v.x), __float2half_rn(v.y)),
                   packh2(__float2half_rn(v.z), __float2half_rn(v.w)));
}

// ---------------------------------------------------------------------------
// Kernel 2: 2:4 mask (strict-< argmin matches top_k tie-break) + fp16
// ---------------------------------------------------------------------------
__global__ void maskw_kernel(const float* __restrict__ w) {
    int g = blockIdx.x * blockDim.x + threadIdx.x;
    const int NG = DOUT * DIN / 4;
    if (g >= NG) return;
    float4 wv = reinterpret_cast<const float4*>(w)[g];
    float v[4] = {wv.x, wv.y, wv.z, wv.w};
    float a[4] = {fabsf(wv.x), fabsf(wv.y), fabsf(wv.z), fabsf(wv.w)};
    int i0 = 0;
#pragma unroll
    for (int i = 1; i < 4; i++) if (a[i] < a[i0]) i0 = i;
    int i1 = (i0 == 0) ? 1 : 0;
#pragma unroll
    for (int i = 0; i < 4; i++) if (i != i0 && a[i] < a[i1]) i1 = i;
    v[i0] = 0.0f; v[i1] = 0.0f;
    reinterpret_cast<uint2*>(g_wh)[g] =
        make_uint2(packh2(__float2half_rn(v[0]), __float2half_rn(v[1])),
                   packh2(__float2half_rn(v[2]), __float2half_rn(v[3])));
}

// ---------------------------------------------------------------------------
// Chunk loader: 2 tiles (x, w), each 128 rows x 128 B, SW128 swizzled.
// 8 x 16B cp.async per thread.
// ---------------------------------------------------------------------------
__device__ __forceinline__ void load_chunk(int c, int s, uint32_t sb,
                                           int m0, int n0, int tid) {
    const uint4* srcs[2] = {
        reinterpret_cast<const uint4*>(g_xh) + (size_t)m0 * ROWU4,
        reinterpret_cast<const uint4*>(g_wh) + (size_t)n0 * ROWU4};
#pragma unroll
    for (int tile = 0; tile < 2; tile++) {
        const uint4* src = srcs[tile] + c * 8;
        uint32_t tb = sb + s * STAGE_B + tile * TILE_B;
#pragma unroll
        for (int i = 0; i < 4; i++) {
            int idx = i * 256 + tid;
            int row = idx >> 3;
            int c16 = idx & 7;
            uint32_t off = (uint32_t)(row * 128 + c16 * 16);
            off ^= (off >> 3) & 0x70;
            cp16(tb + off, src + (size_t)row * ROWU4 + c16);
        }
    }
}

// ---------------------------------------------------------------------------
// Kernel 3: single-pass fp16 HMMA GEMM.
// 8 warps, warp grid 2(M) x 4(N), warp tile 64x32.
// ---------------------------------------------------------------------------
__global__ __launch_bounds__(256, 2)
void gemm_hmma_kernel(const float* __restrict__ bias, float* __restrict__ C) {
    extern __shared__ __align__(1024) char smem[];
    const uint32_t sb = smem_u32(smem);
    const int tid = threadIdx.x;
    const int lane = tid & 31;
    const int wid = tid >> 5;
    const int wm = wid & 1;        // 0..1  (M)
    const int wn = wid >> 1;       // 0..3  (N)
    const int m0 = blockIdx.y * BM;
    const int n0 = blockIdx.x * BN;

    float acc[4][4][4];
#pragma unroll
    for (int t = 0; t < 4; t++)
#pragma unroll
        for (int j = 0; j < 4; j++)
#pragma unroll
            for (int k = 0; k < 4; k++) acc[t][j][k] = 0.0f;

    // prologue: 2 chunks in flight
    load_chunk(0, 0, sb, m0, n0, tid); cp_commit();
    load_chunk(1, 1, sb, m0, n0, tid); cp_commit();

    for (int c = 0; c < NCHUNK; c++) {
        if (c == NCHUNK - 1) asm volatile("cp.async.wait_group 0;" ::: "memory");
        else                 asm volatile("cp.async.wait_group 1;" ::: "memory");
        __syncthreads();

        const int s = c & 1;
        const uint32_t aT = sb + s * STAGE_B;
        const uint32_t bT = aT + TILE_B;

#pragma unroll
        for (int ks = 0; ks < 4; ks++) {
            uint32_t af[4][4];
#pragma unroll
            for (int t = 0; t < 4; t++) {
                uint32_t off = (uint32_t)((wm * 64 + t * 16 + (lane & 15)) * 128
                                          + ks * 32 + (lane >> 4) * 16);
                off ^= (off >> 3) & 0x70;
                ldmx4(af[t], aT + off);
            }
            uint32_t bf[4][2];
#pragma unroll
            for (int jj = 0; jj < 2; jj++) {
                uint32_t row = (uint32_t)(wn * 32 + jj * 16
                                          + ((lane >> 4) & 1) * 8 + (lane & 7));
                uint32_t off = row * 128 + ks * 32 + ((lane >> 3) & 1) * 16;
                off ^= (off >> 3) & 0x70;
                uint32_t r[4];
                ldmx4(r, bT + off);
                bf[2 * jj][0] = r[0]; bf[2 * jj][1] = r[1];
                bf[2 * jj + 1][0] = r[2]; bf[2 * jj + 1][1] = r[3];
            }
#pragma unroll
            for (int t = 0; t < 4; t++)
#pragma unroll
                for (int j = 0; j < 4; j++) mma_f16(acc[t][j], af[t], bf[j]);
        }

        if (c + 2 < NCHUNK) {
            __syncthreads();
            load_chunk(c + 2, s, sb, m0, n0, tid);
            cp_commit();
        }
    }

    // epilogue: bias add + float2 stores
    const int mrow = lane >> 2;          // 0..7
    const int ncol = (lane & 3) * 2;
#pragma unroll
    for (int t = 0; t < 4; t++) {
        const int mbase = m0 + wm * 64 + t * 16;
#pragma unroll
        for (int j = 0; j < 4; j++) {
            const int n = n0 + wn * 32 + j * 8 + ncol;
            const float2 bv = *reinterpret_cast<const float2*>(bias + n);
            const int m1 = mbase + mrow;
            if (m1 < MTOT) {
                float2 o = make_float2(acc[t][j][0] + bv.x, acc[t][j][1] + bv.y);
                *reinterpret_cast<float2*>(C + (size_t)m1 * DOUT + n) = o;
            }
            const int m2 = m1 + 8;
            if (m2 < MTOT) {
                float2 o = make_float2(acc[t][j][2] + bv.x, acc[t][j][3] + bv.y);
                *reinterpret_cast<float2*>(C + (size_t)m2 * DOUT + n) = o;
            }
        }
    }
}

// ---------------------------------------------------------------------------
extern "C" void kernel_launch(void* const* d_in, const int* in_sizes, int n_in,
                              void* d_out, int out_size) {
    const float* x = nullptr;
    const float* w = nullptr;
    const float* b = nullptr;
    for (int i = 0; i < n_in; i++) {
        if (in_sizes[i] == DOUT * DIN)  w = (const float*)d_in[i];
        else if (in_sizes[i] == DOUT)   b = (const float*)d_in[i];
        else                            x = (const float*)d_in[i];
    }
    float* out = (float*)d_out;

    cudaFuncSetAttribute(gemm_hmma_kernel,
                         cudaFuncAttributeMaxDynamicSharedMemorySize,
                         SMEM_TOTAL);

    const int ngx = MPAD * (DIN / 4);
    convx_kernel<<<(ngx + 255) / 256, 256>>>(x);
    const int ngw = DOUT * DIN / 4;
    maskw_kernel<<<(ngw + 255) / 256, 256>>>(w);

    dim3 grid(DOUT / BN, MPAD / BM);
    gemm_hmma_kernel<<<grid, 256, SMEM_TOTAL>>>(b, out);
}